// round 6
// baseline (speedup 1.0000x reference)
#include <cuda_runtime.h>

// CoupledClustersLossV2 — persistent single-wave, single-pass, HBM-bound.
// embeddings: [256 cls][2 pos/neg][32 samples][2048] fp32 = 128 MB.
// ||x - a||^2 = ||x||^2 - (x·s)/16 + ||s||^2/1024,  s = sum of 32 pos rows;
// decomposes over D-chunks -> each class split into 8 D-slices (items).
// Grid = 296 CTAs (exactly 2/SM), each CTA streams ~7 items with a register
// double-buffer prefetch that never drains (across chunks AND items).
// Per-class combine + global mean fused via epoch counters (replay-safe).

#define NCLS    256
#define NS      32
#define DIM     2048
#define NPART   8
#define DPART   (DIM / NPART)          // 256 cols per item
#define CHUNK   128
#define NCH     (DPART / CHUNK)        // 2 chunks per item
#define GRID    296                    // 2 CTAs per SM, single wave
#define THREADS 256
#define NITEMS  (NCLS * NPART)         // 2048
#define ITEMS_LO (NITEMS / GRID)       // 6
#define ITEMS_REM (NITEMS - ITEMS_LO * GRID)   // 272
#define MARGIN  0.3f

// per-(class,part) row partials: 0=||pos||^2 1=pos·s 2=||neg||^2 3=neg·s
__device__ float        g_scratch[NCLS][NPART][4][NS];
__device__ unsigned int g_done[NCLS];     // epoch counters (never reset)
__device__ float        g_class_loss[NCLS];
__device__ unsigned int g_cls_done;       // epoch counter (never reset)

__device__ __forceinline__ float dot4(float4 a, float4 b) {
    return fmaf(a.x, b.x, fmaf(a.y, b.y, fmaf(a.z, b.z, a.w * b.w)));
}
__device__ __forceinline__ float wsum(float v) {
#pragma unroll
    for (int o = 16; o > 0; o >>= 1) v += __shfl_xor_sync(0xffffffffu, v, o);
    return v;
}

__global__ __launch_bounds__(THREADS, 2)
void ccl_kernel(const float* __restrict__ emb, float* __restrict__ out)
{
    __shared__ float spart[2][8][CHUNK];   // double-buffered warp colsum partials (8 KB)

    const int bid  = blockIdx.x;
    const int tid  = threadIdx.x;
    const int warp = tid >> 5;
    const int lane = tid & 31;

    const int n_items = (bid < ITEMS_REM) ? (ITEMS_LO + 1) : ITEMS_LO;
    const int nchunks = n_items * NCH;

    // float4 base for chunk c of this CTA's flat chunk list.
    // Thread covers pos rows {warp+8it} / neg rows {32+warp+8it}, f4-col = lane.
    auto chunk_base = [&](int c) -> const float4* {
        const int item = bid + (c >> 1) * GRID;        // NCH == 2
        const int cls  = item >> 3;                    // NPART == 8
        const int part = item & 7;
        const float* base = emb + ((size_t)cls << 17)  // 2*NS*DIM = 131072
                                + (size_t)((part << 8) + ((c & 1) << 7));
        return (const float4*)base + (size_t)warp * (DIM / 4) + lane;
    };

    // Register double-buffered tiles: 32 rows x 128 cols, pos + neg.
    float4 pb[2][4], nb[2][4];
    {
        const float4* b4 = chunk_base(0);
#pragma unroll
        for (int it = 0; it < 4; ++it) {
            pb[0][it] = b4[it * 8 * (DIM / 4)];
            nb[0][it] = b4[(NS + it * 8) * (DIM / 4)];
        }
    }

    float pn[4], tp[4], nn[4], tn[4];

    for (int c = 0; c < nchunks; ++c) {
        const int cur = c & 1, nxt = cur ^ 1;

        // Prefetch next chunk (crosses item boundaries -> pipeline never drains).
        if (c + 1 < nchunks) {
            const float4* b4 = chunk_base(c + 1);
#pragma unroll
            for (int it = 0; it < 4; ++it) {
                pb[nxt][it] = b4[it * 8 * (DIM / 4)];
                nb[nxt][it] = b4[(NS + it * 8) * (DIM / 4)];
            }
        }

        if (cur == 0) {   // item start: reset accumulators
#pragma unroll
            for (int it = 0; it < 4; ++it) { pn[it] = tp[it] = nn[it] = tn[it] = 0.f; }
        }

        // Per-warp partial column sums of this warp's 4 pos rows.
        float4 sp;
        sp.x = (pb[cur][0].x + pb[cur][1].x) + (pb[cur][2].x + pb[cur][3].x);
        sp.y = (pb[cur][0].y + pb[cur][1].y) + (pb[cur][2].y + pb[cur][3].y);
        sp.z = (pb[cur][0].z + pb[cur][1].z) + (pb[cur][2].z + pb[cur][3].z);
        sp.w = (pb[cur][0].w + pb[cur][1].w) + (pb[cur][2].w + pb[cur][3].w);
        *(float4*)&spart[cur][warp][lane * 4] = sp;

        // Row norms straight from registers (overlaps with STS latency).
#pragma unroll
        for (int it = 0; it < 4; ++it) {
            pn[it] += dot4(pb[cur][it], pb[cur][it]);
            nn[it] += dot4(nb[cur][it], nb[cur][it]);
        }
        __syncthreads();   // the ONLY per-chunk barrier

        // Full column sums: each thread sums the 8 warp partials for its f4.
        float4 sc = *(const float4*)&spart[cur][0][lane * 4];
#pragma unroll
        for (int w = 1; w < 8; ++w) {
            float4 t = *(const float4*)&spart[cur][w][lane * 4];
            sc.x += t.x; sc.y += t.y; sc.z += t.z; sc.w += t.w;
        }
        // (next chunk writes spart[nxt]; spart[cur] reused only after
        //  chunk c+1's barrier -> no trailing barrier needed)

#pragma unroll
        for (int it = 0; it < 4; ++it) {
            tp[it] += dot4(pb[cur][it], sc);
            tn[it] += dot4(nb[cur][it], sc);
        }

        if (cur == 1) {
            // ---- item flush (next chunk's LDGs already in flight) ----
            const int item = bid + (c >> 1) * GRID;
            const int cls  = item >> 3;
            const int part = item & 7;
#pragma unroll
            for (int it = 0; it < 4; ++it) {
                const float a = wsum(pn[it]);
                const float b = wsum(tp[it]);
                const float d = wsum(nn[it]);
                const float e = wsum(tn[it]);
                if (lane == 0) {
                    const int row = warp + it * 8;
                    g_scratch[cls][part][0][row] = a;
                    g_scratch[cls][part][1][row] = b;
                    g_scratch[cls][part][2][row] = d;
                    g_scratch[cls][part][3][row] = e;
                }
            }
            if (lane == 0) __threadfence();
            __syncthreads();

            unsigned fin = 0;
            if (tid == 0) {
                const unsigned old = atomicAdd(&g_done[cls], 1u);
                fin = ((old & (NPART - 1u)) == (NPART - 1u)) ? 1u : 0u;
            }
            if (warp == 0) {
                fin = __shfl_sync(0xffffffffu, fin, 0);
                if (fin) {
                    // ---- per-class finisher (warp 0 only, no barriers) ----
                    __threadfence();
                    float fpn = 0.f, ftp = 0.f, fnn = 0.f, ftn = 0.f;
#pragma unroll
                    for (int p = 0; p < NPART; ++p) {   // fixed order
                        fpn += __ldcg(&g_scratch[cls][p][0][lane]);
                        ftp += __ldcg(&g_scratch[cls][p][1][lane]);
                        fnn += __ldcg(&g_scratch[cls][p][2][lane]);
                        ftn += __ldcg(&g_scratch[cls][p][3][lane]);
                    }
                    const float ssum  = wsum(ftp);             // ||s||^2
                    const float anorm = ssum * (1.0f / 1024.0f);
                    const float ap2   = fpn - ftp * (1.0f / 16.0f) + anorm;
                    const float nd2   = fnn - ftn * (1.0f / 16.0f) + anorm;

                    float mn = nd2;
#pragma unroll
                    for (int o = 16; o > 0; o >>= 1)
                        mn = fminf(mn, __shfl_xor_sync(0xffffffffu, mn, o));
                    const float an = sqrtf(fmaxf(mn, 0.f));

                    float t = fmaxf(sqrtf(fmaxf(ap2, 0.f)) - an + MARGIN, 0.f);
                    const float term = wsum(t * t);

                    unsigned old2 = 0;
                    if (lane == 0) {
                        g_class_loss[cls] = term;
                        __threadfence();
                        old2 = atomicAdd(&g_cls_done, 1u);
                    }
                    old2 = __shfl_sync(0xffffffffu, old2, 0);
                    if ((old2 & (NCLS - 1u)) == (NCLS - 1u)) {
                        // ---- global finisher: fixed-order mean ----
                        __threadfence();
                        float v = 0.f;
#pragma unroll
                        for (int q = 0; q < NCLS / 32; ++q)
                            v += __ldcg(&g_class_loss[q * 32 + lane]);
                        v = wsum(v);
                        if (lane == 0) out[0] = v * (1.0f / (float)NCLS);
                    }
                }
            }
        }
    }
}

extern "C" void kernel_launch(void* const* d_in, const int* in_sizes, int n_in,
                              void* d_out, int out_size)
{
    (void)in_sizes; (void)n_in; (void)out_size;
    const float* emb = (const float*)d_in[0];   // [16384, 2048] fp32
    // d_in[1] (target) is unused by the reference computation.
    ccl_kernel<<<GRID, THREADS>>>(emb, (float*)d_out);
}

// round 7
// speedup vs baseline: 1.4099x; 1.4099x over previous
#include <cuda_runtime.h>

// CoupledClustersLossV2 — persistent single-wave, single-pass, HBM-bound.
// embeddings: [256 cls][2 pos/neg][32 samples][2048] fp32 = 128 MB.
// ||x - a||^2 = ||x||^2 - (x·s)/16 + ||s||^2/1024,  s = sum of 32 pos rows;
// decomposes over D-chunks -> each class split into 8 D-slices (items).
// Grid = 296 CTAs (exactly 2/SM, one wave). Each CTA streams 6-7 items.
// ALL buffer indices are compile-time static (R5's dynamic register-array
// indexing spilled to local memory: L1 36% > DRAM 28%). Two named register
// buffer sets (A/B) double-buffer the DRAM stream across chunk AND item
// boundaries so the memory pipe never drains.

#define NCLS     256
#define NS       32
#define DIM      2048
#define NPART    8
#define CHUNK    128
#define GRID     296
#define THREADS  256
#define NITEMS   (NCLS * NPART)               // 2048
#define ITEMS_LO (NITEMS / GRID)              // 6
#define ITEMS_REM (NITEMS - ITEMS_LO * GRID)  // 272
#define ROWSTRIDE (DIM / 4)                   // float4 stride between rows
#define MARGIN   0.3f

// per-(class,part) row partials: 0=||pos||^2 1=pos·s 2=||neg||^2 3=neg·s
__device__ float        g_scratch[NCLS][NPART][4][NS];
__device__ unsigned int g_done[NCLS];     // epoch counters (never reset)
__device__ float        g_class_loss[NCLS];
__device__ unsigned int g_cls_done;       // epoch counter (never reset)

__device__ __forceinline__ float dot4(float4 a, float4 b) {
    return fmaf(a.x, b.x, fmaf(a.y, b.y, fmaf(a.z, b.z, a.w * b.w)));
}
__device__ __forceinline__ float wsum(float v) {
#pragma unroll
    for (int o = 16; o > 0; o >>= 1) v += __shfl_xor_sync(0xffffffffu, v, o);
    return v;
}

__shared__ float spart[2][8][CHUNK];   // double-buffered warp colsum partials

// Load one 32x128 pos+neg chunk tile into a named register buffer set.
__device__ __forceinline__ void load_tile(const float4* __restrict__ b4,
                                          float4 (&p)[4], float4 (&n)[4]) {
#pragma unroll
    for (int it = 0; it < 4; ++it) {
        p[it] = b4[(size_t)(it * 8) * ROWSTRIDE];
        n[it] = b4[(size_t)(NS + it * 8) * ROWSTRIDE];
    }
}

// Consume one chunk tile: column sums via spart[SB], norms + dots into accums.
template <int SB>
__device__ __forceinline__ void compute_tile(const float4 (&p)[4], const float4 (&n)[4],
                                             int warp, int lane,
                                             float (&pn)[4], float (&tp)[4],
                                             float (&nn)[4], float (&tn)[4]) {
    float4 sp;
    sp.x = (p[0].x + p[1].x) + (p[2].x + p[3].x);
    sp.y = (p[0].y + p[1].y) + (p[2].y + p[3].y);
    sp.z = (p[0].z + p[1].z) + (p[2].z + p[3].z);
    sp.w = (p[0].w + p[1].w) + (p[2].w + p[3].w);
    *(float4*)&spart[SB][warp][lane * 4] = sp;

#pragma unroll
    for (int it = 0; it < 4; ++it) {
        pn[it] += dot4(p[it], p[it]);
        nn[it] += dot4(n[it], n[it]);
    }
    __syncthreads();

    float4 sc = *(const float4*)&spart[SB][0][lane * 4];
#pragma unroll
    for (int w = 1; w < 8; ++w) {
        float4 t = *(const float4*)&spart[SB][w][lane * 4];
        sc.x += t.x; sc.y += t.y; sc.z += t.z; sc.w += t.w;
    }
#pragma unroll
    for (int it = 0; it < 4; ++it) {
        tp[it] += dot4(p[it], sc);
        tn[it] += dot4(n[it], sc);
    }
    // spart[SB] is rewritten only after the OTHER buffer's barrier -> safe.
}

__global__ __launch_bounds__(THREADS, 2)
void ccl_kernel(const float* __restrict__ emb, float* __restrict__ out)
{
    const int bid  = blockIdx.x;
    const int tid  = threadIdx.x;
    const int warp = tid >> 5;
    const int lane = tid & 31;

    const int n_items = (bid < ITEMS_REM) ? (ITEMS_LO + 1) : ITEMS_LO;

    // float4 base pointer for (item, chunk); thread offset = warp row + lane col.
    auto item_ptr = [&](int item, int chunk) -> const float4* {
        const int cls  = item >> 3;                    // NPART == 8
        const int part = item & 7;
        const float* b = emb + ((size_t)cls << 17)     // 2*NS*DIM
                             + (size_t)((part << 8) + (chunk << 7));
        return (const float4*)b + (size_t)warp * ROWSTRIDE + lane;
    };

    float4 pA[4], nA[4], pB[4], nB[4];

    // Prologue: item0 chunk0 -> A.
    load_tile(item_ptr(bid, 0), pA, nA);

    for (int i = 0; i < n_items; ++i) {
        const int item = bid + i * GRID;

        // Prefetch chunk1 -> B (in flight during compute(A)).
        load_tile(item_ptr(item, 1), pB, nB);

        float pn[4] = {0.f,0.f,0.f,0.f};
        float tp[4] = {0.f,0.f,0.f,0.f};
        float nn[4] = {0.f,0.f,0.f,0.f};
        float tn[4] = {0.f,0.f,0.f,0.f};

        compute_tile<0>(pA, nA, warp, lane, pn, tp, nn, tn);

        // Prefetch next item's chunk0 -> A (in flight during compute(B)+flush).
        if (i + 1 < n_items)
            load_tile(item_ptr(item + GRID, 0), pA, nA);

        compute_tile<1>(pB, nB, warp, lane, pn, tp, nn, tn);

        // ---- item flush (next chunk's LDGs already in flight) ----
        const int cls  = item >> 3;
        const int part = item & 7;
#pragma unroll
        for (int it = 0; it < 4; ++it) {
            const float a = wsum(pn[it]);
            const float b = wsum(tp[it]);
            const float d = wsum(nn[it]);
            const float e = wsum(tn[it]);
            if (lane == 0) {
                const int row = warp + it * 8;
                g_scratch[cls][part][0][row] = a;
                g_scratch[cls][part][1][row] = b;
                g_scratch[cls][part][2][row] = d;
                g_scratch[cls][part][3][row] = e;
            }
        }
        if (lane == 0) __threadfence();
        __syncthreads();   // all 16 scratch rows written before the count

        unsigned fin = 0;
        if (tid == 0) {
            const unsigned old = atomicAdd(&g_done[cls], 1u);
            fin = ((old & (NPART - 1u)) == (NPART - 1u)) ? 1u : 0u;
        }
        if (warp == 0) {
            fin = __shfl_sync(0xffffffffu, fin, 0);
            if (fin) {
                // ---- per-class finisher (warp 0 only, no barriers) ----
                __threadfence();
                float fpn = 0.f, ftp = 0.f, fnn = 0.f, ftn = 0.f;
#pragma unroll
                for (int p = 0; p < NPART; ++p) {   // fixed order: deterministic
                    fpn += __ldcg(&g_scratch[cls][p][0][lane]);
                    ftp += __ldcg(&g_scratch[cls][p][1][lane]);
                    fnn += __ldcg(&g_scratch[cls][p][2][lane]);
                    ftn += __ldcg(&g_scratch[cls][p][3][lane]);
                }
                const float ssum  = wsum(ftp);             // ||s||^2
                const float anorm = ssum * (1.0f / 1024.0f);
                const float ap2   = fpn - ftp * (1.0f / 16.0f) + anorm;
                const float nd2   = fnn - ftn * (1.0f / 16.0f) + anorm;

                float mn = nd2;
#pragma unroll
                for (int o = 16; o > 0; o >>= 1)
                    mn = fminf(mn, __shfl_xor_sync(0xffffffffu, mn, o));
                const float an = sqrtf(fmaxf(mn, 0.f));

                float t = fmaxf(sqrtf(fmaxf(ap2, 0.f)) - an + MARGIN, 0.f);
                const float term = wsum(t * t);

                unsigned old2 = 0;
                if (lane == 0) {
                    g_class_loss[cls] = term;
                    __threadfence();
                    old2 = atomicAdd(&g_cls_done, 1u);
                }
                old2 = __shfl_sync(0xffffffffu, old2, 0);
                if ((old2 & (NCLS - 1u)) == (NCLS - 1u)) {
                    // ---- global finisher: fixed-order mean over 256 losses ----
                    __threadfence();
                    float v = 0.f;
#pragma unroll
                    for (int q = 0; q < NCLS / 32; ++q)
                        v += __ldcg(&g_class_loss[q * 32 + lane]);
                    v = wsum(v);
                    if (lane == 0) out[0] = v * (1.0f / (float)NCLS);
                }
            }
        }
    }
}

extern "C" void kernel_launch(void* const* d_in, const int* in_sizes, int n_in,
                              void* d_out, int out_size)
{
    (void)in_sizes; (void)n_in; (void)out_size;
    const float* emb = (const float*)d_in[0];   // [16384, 2048] fp32
    // d_in[1] (target) is unused by the reference computation.
    ccl_kernel<<<GRID, THREADS>>>(emb, (float*)d_out);
}

// round 8
// speedup vs baseline: 1.4198x; 1.0070x over previous
#include <cuda_runtime.h>

// CoupledClustersLossV2 — persistent single-wave, cp.async-staged, HBM-bound.
// embeddings: [256 cls][2 pos/neg][32 samples][2048] fp32 = 128 MB.
// ||x - a||^2 = ||x||^2 - (x·s)/16 + ||s||^2/1024,  s = sum of 32 pos rows;
// decomposes over D-chunks -> each class split into 8 D-slices (items).
//
// R5/R6 lesson: register double-buffering of the stream needs 64+ regs and
// spills at the launch_bounds(256,2) cap (regs=128, L1% high). Here the
// GMEM->SMEM path is cp.async.cg (LDGSTS): zero registers in flight, L1
// bypassed. Two 32KB SMEM stages/CTA keep >=64KB/SM of copies outstanding.
// Consumer reads each tile ONCE into statically-indexed registers.
// Grid = 296 CTAs (exactly 2/SM, one wave); finishers fused via epoch counters.

#define NCLS     256
#define NS       32
#define DIM      2048
#define NPART    8
#define CHUNK    128
#define GRID     296
#define THREADS  256
#define NITEMS   (NCLS * NPART)               // 2048
#define ITEMS_LO (NITEMS / GRID)              // 6
#define ITEMS_REM (NITEMS - ITEMS_LO * GRID)  // 272
#define TILE_F4  2048                         // 64 rows x 32 float4
#define SMEM_BYTES (2 * TILE_F4 * 16 + 2 * 8 * CHUNK * 4)   // 73728
#define MARGIN   0.3f

// per-(class,part) row partials: 0=||pos||^2 1=pos·s 2=||neg||^2 3=neg·s
__device__ float        g_scratch[NCLS][NPART][4][NS];
__device__ unsigned int g_done[NCLS];     // epoch counters (never reset)
__device__ float        g_class_loss[NCLS];
__device__ unsigned int g_cls_done;       // epoch counter (never reset)

__device__ __forceinline__ float dot4(float4 a, float4 b) {
    return fmaf(a.x, b.x, fmaf(a.y, b.y, fmaf(a.z, b.z, a.w * b.w)));
}
__device__ __forceinline__ float wsum(float v) {
#pragma unroll
    for (int o = 16; o > 0; o >>= 1) v += __shfl_xor_sync(0xffffffffu, v, o);
    return v;
}
__device__ __forceinline__ void cp_async16(float4* smem_dst, const float4* gsrc) {
    unsigned dst = (unsigned)__cvta_generic_to_shared(smem_dst);
    asm volatile("cp.async.cg.shared.global [%0], [%1], 16;\n"
                 :: "r"(dst), "l"(gsrc));
}

// Issue one 64x128 (pos+neg) chunk tile GMEM->SMEM. Thread (warp, lane)
// copies rows {warp + 8i, i=0..7} at f4-column `lane` — the SAME slots its
// consumer phase later reads (rows are class-contiguous: pos 0-31, neg 32-63).
__device__ __forceinline__ void issue_chunk(const float* __restrict__ emb,
                                            int item, int half,
                                            float4* __restrict__ tile,
                                            int warp, int lane) {
    const int cls  = item >> 3;                 // NPART == 8
    const int part = item & 7;
    const float4* g = (const float4*)(emb + ((size_t)cls << 17))   // 2*NS*DIM
                      + (part << 6) + (half << 5) + lane;
#pragma unroll
    for (int i = 0; i < 8; ++i) {
        const int row = warp + i * 8;
        cp_async16(&tile[row * 32 + lane], g + (size_t)row * (DIM / 4));
    }
    asm volatile("cp.async.commit_group;\n" ::);
}

__global__ __launch_bounds__(THREADS, 2)
void ccl_kernel(const float* __restrict__ emb, float* __restrict__ out)
{
    extern __shared__ float4 sh4[];                  // [2][TILE_F4] tiles
    float* spart = (float*)(sh4 + 2 * TILE_F4);      // [2][8][CHUNK] colsum partials

    const int bid  = blockIdx.x;
    const int tid  = threadIdx.x;
    const int warp = tid >> 5;
    const int lane = tid & 31;

    const int n_items = (bid < ITEMS_REM) ? (ITEMS_LO + 1) : ITEMS_LO;
    const int nchunks = n_items * 2;                 // 2 chunks (halves) per item

    // Prologue: fill both stages.
    issue_chunk(emb, bid, 0, sh4,            warp, lane);
    issue_chunk(emb, bid, 1, sh4 + TILE_F4,  warp, lane);

    float pn[4], tp[4], nn[4], tn[4];

    for (int c = 0; c < nchunks; ++c) {
        const int s = c & 1;                         // stage == half (NCH==2)

        if (c + 1 < nchunks) asm volatile("cp.async.wait_group 1;\n" ::);
        else                 asm volatile("cp.async.wait_group 0;\n" ::);
        __syncthreads();                             // tile c visible to all

        // Read this warp's 4 pos + 4 neg rows ONCE into registers.
        const float4* tile = sh4 + s * TILE_F4;
        float4 p[4], n[4];
#pragma unroll
        for (int it = 0; it < 4; ++it) {
            p[it] = tile[(warp + it * 8) * 32 + lane];
            n[it] = tile[(32 + warp + it * 8) * 32 + lane];
        }

        if (s == 0) {                                // item start
#pragma unroll
            for (int it = 0; it < 4; ++it) { pn[it] = tp[it] = nn[it] = tn[it] = 0.f; }
        }

        // Per-warp partial column sums of the 4 pos rows.
        float4 spv;
        spv.x = (p[0].x + p[1].x) + (p[2].x + p[3].x);
        spv.y = (p[0].y + p[1].y) + (p[2].y + p[3].y);
        spv.z = (p[0].z + p[1].z) + (p[2].z + p[3].z);
        spv.w = (p[0].w + p[1].w) + (p[2].w + p[3].w);
        *(float4*)&spart[(s * 8 + warp) * CHUNK + lane * 4] = spv;

        // Row norms (overlap STS latency).
#pragma unroll
        for (int it = 0; it < 4; ++it) {
            pn[it] += dot4(p[it], p[it]);
            nn[it] += dot4(n[it], n[it]);
        }
        __syncthreads();     // spart ready; tile stage s fully consumed into regs

        // Full column sums for this thread's 4 columns.
        float4 sc = *(const float4*)&spart[(s * 8 + 0) * CHUNK + lane * 4];
#pragma unroll
        for (int w = 1; w < 8; ++w) {
            float4 t = *(const float4*)&spart[(s * 8 + w) * CHUNK + lane * 4];
            sc.x += t.x; sc.y += t.y; sc.z += t.z; sc.w += t.w;
        }
#pragma unroll
        for (int it = 0; it < 4; ++it) {
            tp[it] += dot4(p[it], sc);
            tn[it] += dot4(n[it], sc);
        }

        // Refill stage s with chunk c+2 (copies fly during next chunk + flush).
        if (c + 2 < nchunks) {
            const int cc = c + 2;
            issue_chunk(emb, bid + (cc >> 1) * GRID, cc & 1,
                        sh4 + s * TILE_F4, warp, lane);
        }

        if (s == 1) {
            // ---- item flush (next copies already in flight) ----
            const int item = bid + (c >> 1) * GRID;
            const int cls  = item >> 3;
            const int part = item & 7;
#pragma unroll
            for (int it = 0; it < 4; ++it) {
                const float a = wsum(pn[it]);
                const float b = wsum(tp[it]);
                const float d = wsum(nn[it]);
                const float e = wsum(tn[it]);
                if (lane == 0) {
                    const int row = warp + it * 8;
                    g_scratch[cls][part][0][row] = a;
                    g_scratch[cls][part][1][row] = b;
                    g_scratch[cls][part][2][row] = d;
                    g_scratch[cls][part][3][row] = e;
                }
            }
            if (lane == 0) __threadfence();
            __syncthreads();       // all 16 scratch rows written before count

            unsigned fin = 0;
            if (tid == 0) {
                const unsigned old = atomicAdd(&g_done[cls], 1u);
                fin = ((old & (NPART - 1u)) == (NPART - 1u)) ? 1u : 0u;
            }
            if (warp == 0) {
                fin = __shfl_sync(0xffffffffu, fin, 0);
                if (fin) {
                    // ---- per-class finisher (warp 0 only) ----
                    __threadfence();
                    float fpn = 0.f, ftp = 0.f, fnn = 0.f, ftn = 0.f;
#pragma unroll
                    for (int pp = 0; pp < NPART; ++pp) {   // fixed order
                        fpn += __ldcg(&g_scratch[cls][pp][0][lane]);
                        ftp += __ldcg(&g_scratch[cls][pp][1][lane]);
                        fnn += __ldcg(&g_scratch[cls][pp][2][lane]);
                        ftn += __ldcg(&g_scratch[cls][pp][3][lane]);
                    }
                    const float ssum  = wsum(ftp);              // ||s||^2
                    const float anorm = ssum * (1.0f / 1024.0f);
                    const float ap2   = fpn - ftp * (1.0f / 16.0f) + anorm;
                    const float nd2   = fnn - ftn * (1.0f / 16.0f) + anorm;

                    float mn = nd2;
#pragma unroll
                    for (int o = 16; o > 0; o >>= 1)
                        mn = fminf(mn, __shfl_xor_sync(0xffffffffu, mn, o));
                    const float an = sqrtf(fmaxf(mn, 0.f));

                    float t = fmaxf(sqrtf(fmaxf(ap2, 0.f)) - an + MARGIN, 0.f);
                    const float term = wsum(t * t);

                    unsigned old2 = 0;
                    if (lane == 0) {
                        g_class_loss[cls] = term;
                        __threadfence();
                        old2 = atomicAdd(&g_cls_done, 1u);
                    }
                    old2 = __shfl_sync(0xffffffffu, old2, 0);
                    if ((old2 & (NCLS - 1u)) == (NCLS - 1u)) {
                        // ---- global finisher: fixed-order mean ----
                        __threadfence();
                        float v = 0.f;
#pragma unroll
                        for (int q = 0; q < NCLS / 32; ++q)
                            v += __ldcg(&g_class_loss[q * 32 + lane]);
                        v = wsum(v);
                        if (lane == 0) out[0] = v * (1.0f / (float)NCLS);
                    }
                }
            }
        }
    }
}

extern "C" void kernel_launch(void* const* d_in, const int* in_sizes, int n_in,
                              void* d_out, int out_size)
{
    (void)in_sizes; (void)n_in; (void)out_size;
    const float* emb = (const float*)d_in[0];   // [16384, 2048] fp32
    // d_in[1] (target) is unused by the reference computation.
    cudaFuncSetAttribute(ccl_kernel, cudaFuncAttributeMaxDynamicSharedMemorySize,
                         SMEM_BYTES);
    ccl_kernel<<<GRID, THREADS, SMEM_BYTES>>>(emb, (float*)d_out);
}